// round 15
// baseline (speedup 1.0000x reference)
#include <cuda_runtime.h>

#define BB    16
#define NN    4096
#define CC    64
#define KNNK  32
#define QB    256
#define NPAIRS 2048                      // all 4096 candidates resident
#define HP    1024                       // pairs per half
#define CAP   320

#define F_INF  __int_as_float(0x7f800000)
#define F_NINF __int_as_float(0xff800000)
#define FULL   0xFFFFFFFFu

typedef unsigned long long ull;

// Scratch (static device globals — allowed; no runtime allocation).
__device__ int   g_idx[BB * NN * KNNK];      // 8 MB
__device__ float g_mx[BB * NN * CC];         // 16 MB
__device__ float g_mn[BB * NN * CC];         // 16 MB
__device__ float g_part[BB * NN / 8];        // 8192 block partials
__device__ float g_inv;

// ---- Blackwell packed f32x2 ops (PTX-only; min/max.f32x2 do NOT exist) ----
__device__ __forceinline__ ull fma2(ull a, ull b, ull c) {
    ull d; asm("fma.rn.f32x2 %0, %1, %2, %3;" : "=l"(d) : "l"(a), "l"(b), "l"(c));
    return d;
}
__device__ __forceinline__ ull mul2(ull a, ull b) {
    ull d; asm("mul.rn.f32x2 %0, %1, %2;" : "=l"(d) : "l"(a), "l"(b));
    return d;
}
__device__ __forceinline__ ull pk2(float lo, float hi) {
    ull r; asm("mov.b64 %0, {%1, %2};" : "=l"(r) : "f"(lo), "f"(hi));
    return r;
}
__device__ __forceinline__ void up2(ull v, float& lo, float& hi) {
    asm("mov.b64 {%0, %1}, %2;" : "=f"(lo), "=f"(hi) : "l"(v));
}

// Branchless insert of c into ascending sorted 32-reg array (fallback only).
__device__ __forceinline__ void insert32(float (&sv)[KNNK], float c) {
#pragma unroll
    for (int u = 0; u < KNNK; u++) {
        float lo = fminf(sv[u], c);
        c = fmaxf(sv[u], c);
        sv[u] = lo;
    }
}

// Dummy no-op kernels: rotate ncu's "-s 5 -c 1" capture slot onto knn_kernel.
__global__ void nop_kernel() {}

// ---------------------------------------------------------------------------
// Kernel 1: exact 32-NN. Block = 128 queries x 2 candidate halves (8 warps):
// warps 0-3 sweep candidates [0,2048) for queries 0..127, warps 4-7 sweep
// [2048,4096) for the same queries — doubles warps/SM (R14 ncu: occ 20%,
// issue 46%, no pipe saturated => latency-bound). Per-thread batched
// selection (R14): accepts append to local record; flush = bitonic sort of
// the <=32-batch + bitonic merge-keep-min-32 into sv. Exact union-32nd + tie
// split across halves (R10-validated, half-0 = lower indices gets priority).
// Replay record for emission; sv repaired from smem before merge on overflow.
// ---------------------------------------------------------------------------
__global__ void __launch_bounds__(QB, 3) knn_kernel(const float* __restrict__ xyz) {
    __shared__ ulonglong2 s_xy[NPAIRS];              // {x01, y01}  32 KB
    __shared__ ull        s_z [NPAIRS];              //  z01        16 KB

    const int b     = blockIdx.x >> 5;               // 32 blocks per batch
    const int lane  = threadIdx.x & 31;
    const int warp  = threadIdx.x >> 5;
    const int h     = warp >> 2;                     // candidate half 0/1
    const int ql    = ((warp & 3) << 5) | lane;      // query local 0..127
    const int i     = ((blockIdx.x & 31) << 7) + ql;
    const float* xb = xyz + (size_t)b * (3 * NN);

    // Load + pack all candidates.
    for (int p = threadIdx.x; p < NPAIRS; p += QB) {
        float2 X = *(const float2*)(xb + 2 * p);
        float2 Y = *(const float2*)(xb + NN + 2 * p);
        float2 Z = *(const float2*)(xb + 2 * NN + 2 * p);
        s_xy[p] = make_ulonglong2(pk2(X.x, X.y), pk2(Y.x, Y.y));
        s_z[p]  = pk2(Z.x, Z.y);
    }

    const float xi = xb[i], yi = xb[NN + i], zi = xb[2 * NN + i];
    const ull AX = pk2(-2.f * xi, -2.f * xi);
    const ull AY = pk2(-2.f * yi, -2.f * yi);
    const ull AZ = pk2(-2.f * zi, -2.f * zi);
    __syncthreads();

    // d_rel = ||xj||^2 - 2 xi.xj, rounding identical to the R6/R8 champion.
    auto dist2 = [&](int p) -> ull {
        ulonglong2 XY = s_xy[p];
        ull Z  = s_z[p];
        ull nn = fma2(XY.x, XY.x, fma2(XY.y, XY.y, mul2(Z, Z)));
        return fma2(AX, XY.x, fma2(AY, XY.y, fma2(AZ, Z, nn)));
    };

    float2 rec[CAP];                                 // local mem (d, idx-bits)
    int rc = 0;                                      // total recorded
    int cnt = 0;                                     // recorded since flush
    bool ofl = false;

    float sv[KNNK];
#pragma unroll
    for (int u = 0; u < KNNK; u++) sv[u] = F_INF;
    float worst = F_INF;

    // Flush: exact top-32 update from the last `cnt` recorded distances.
    auto flush = [&]() {
        float t32[KNNK];
#pragma unroll
        for (int u = 0; u < KNNK; u++) {
            float v = F_INF;
            if (u < cnt) v = rec[rc - cnt + u].x;    // predicated LDL
            t32[u] = v;
        }
        // bitonic sort t32 ascending (ILP-16 network)
#pragma unroll
        for (int k = 2; k <= KNNK; k <<= 1) {
#pragma unroll
            for (int j = k >> 1; j > 0; j >>= 1) {
#pragma unroll
                for (int u = 0; u < KNNK; u++) {
                    int l = u ^ j;
                    if (l > u) {
                        bool up = ((u & k) == 0);
                        float lo = fminf(t32[u], t32[l]);
                        float hi = fmaxf(t32[u], t32[l]);
                        t32[u] = up ? lo : hi;
                        t32[l] = up ? hi : lo;
                    }
                }
            }
        }
        // keep-min-32 of sv ∪ t32: pairwise mins form a bitonic sequence
#pragma unroll
        for (int u = 0; u < KNNK; u++)
            sv[u] = fminf(sv[u], t32[KNNK - 1 - u]);
        // bitonic merge sv ascending (5 stages)
#pragma unroll
        for (int j = KNNK / 2; j > 0; j >>= 1) {
#pragma unroll
            for (int u = 0; u < KNNK; u++) {
                int l = u ^ j;
                if (l > u) {
                    float lo = fminf(sv[u], sv[l]);
                    float hi = fmaxf(sv[u], sv[l]);
                    sv[u] = lo; sv[l] = hi;
                }
            }
        }
        cnt = 0;
        worst = sv[KNNK - 1];
    };

    // ---- sweep my half: record accepts, batched flush ---------------------
    const int p0h = h << 10;                         // first pair of my half
#pragma unroll 4
    for (int p = p0h; p < p0h + HP; p++) {
        if (__any_sync(FULL, cnt >= 31)) flush();
        float d0, d1; up2(dist2(p), d0, d1);
        if (d0 < worst) {
            if (rc < CAP) { rec[rc++] = make_float2(d0, __int_as_float(2 * p)); cnt++; }
            else ofl = true;
        }
        if (d1 < worst) {
            if (rc < CAP) { rec[rc++] = make_float2(d1, __int_as_float(2 * p + 1)); cnt++; }
            else ofl = true;
        }
    }
    flush();                                         // leftovers

    // Repair sv BEFORE merge if the record overflowed (never expected):
    // smem candidates are still intact here.
    if (ofl) {
#pragma unroll
        for (int u = 0; u < KNNK; u++) sv[u] = F_INF;
        for (int p = p0h; p < p0h + HP; p++) {
            float d0, d1; up2(dist2(p), d0, d1);
            if (d0 < sv[KNNK - 1]) insert32(sv, d0);
            if (d1 < sv[KNNK - 1]) insert32(sv, d1);
        }
    }

    // ---- exchange + exact union selection (aliased over candidate smem) --
    float* exf   = reinterpret_cast<float*>(s_z);    // [u*128 + ql], 16 KB
    float* metaW = reinterpret_cast<float*>(s_xy);   // w per query
    int*   metaO = reinterpret_cast<int*>(s_xy) + 128;   // off1
    int*   metaB = reinterpret_cast<int*>(s_xy) + 256;   // bud1

    __syncthreads();                                 // all smem reads done
    if (h == 1) {
#pragma unroll
        for (int u = 0; u < KNNK; u++) exf[u * 128 + ql] = sv[u];
    }
    __syncthreads();

    float w;
    int budget, offset;
    if (h == 0) {
        // merge: exact 32nd smallest of union of my sv and partner's list
        w = F_INF;
#pragma unroll
        for (int t = 0; t <= KNNK; t++) {
            float aa = (t > 0) ? sv[t - 1] : F_NINF;
            float bb = (t < KNNK) ? exf[(KNNK - 1 - t) * 128 + ql] : F_NINF;
            w = fminf(w, fmaxf(aa, bb));
        }
        int less0 = 0, eq0 = 0, less1 = 0;
#pragma unroll
        for (int u = 0; u < KNNK; u++) {
            less0 += (sv[u] < w);
            eq0   += (sv[u] == w);
            less1 += (exf[u * 128 + ql] < w);
        }
        int ties = KNNK - less0 - less1;
        int bud0 = min(eq0, ties);
        budget = bud0;
        offset = 0;
        metaW[ql] = w;
        metaO[ql] = less0 + bud0;
        metaB[ql] = ties - bud0;
    }
    __syncthreads();
    if (h == 1) {
        w      = metaW[ql];
        offset = metaO[ql];
        budget = metaB[ql];
    }

    // ---- emission: replay recorded list (fast path) -----------------------
    const int base = (b * NN + i) * KNNK + offset;
    if (!ofl) {
        int cnt2 = 0;
        for (int t = 0; t < rc; t++) {
            float2 r = rec[t];
            bool lt = r.x < w;
            bool eq = (r.x == w);
            if (lt | (eq & (budget > 0))) {
                g_idx[base + cnt2] = __float_as_int(r.y);
                cnt2++;
                budget -= eq ? 1 : 0;
            }
        }
    } else {
        // ---- fallback (never expected): rescan my half from GLOBAL -------
        // (smem is aliased by the exchange; scalar fmaf chain is
        //  bit-identical to the packed dist2 per lane)
        int cnt2 = 0;
        for (int c = h * 2048; c < h * 2048 + 2048; c++) {
            float X = xb[c], Y = xb[NN + c], Z = xb[2 * NN + c];
            float nn = fmaf(X, X, fmaf(Y, Y, Z * Z));
            float d = fmaf(-2.f * xi, X,
                      fmaf(-2.f * yi, Y, fmaf(-2.f * zi, Z, nn)));
            bool lt = d < w, eq = (d == w);
            if (lt | (eq & (budget > 0))) {
                g_idx[base + cnt2] = c;
                cnt2++;
                budget -= eq ? 1 : 0;
            }
        }
    }
}

// ---------------------------------------------------------------------------
// Kernel 2: warp per (b,i). Lane = channel pair. Coalesced 256B row gathers.
// Produces per-channel max/min of offsets + block partial of sum(offset^2).
// ---------------------------------------------------------------------------
__global__ void __launch_bounds__(256) gather_kernel(const float* __restrict__ feats) {
    const int gw   = (blockIdx.x << 3) + (threadIdx.x >> 5);   // b*NN + i
    const int lane = threadIdx.x & 31;
    const int b = gw >> 12;
    const int i = gw & (NN - 1);
    const float* fb = feats + ((size_t)b << 18);               // b*NN*CC

    const float2 ctr = *(const float2*)(fb + i * CC + lane * 2);
    const int myid = g_idx[gw * KNNK + lane];

    float mx0 = F_NINF, mx1 = F_NINF;
    float mn0 = F_INF,  mn1 = F_INF;
    float ss = 0.f;

#pragma unroll
    for (int k = 0; k < KNNK; k++) {
        int j = __shfl_sync(FULL, myid, k);
        float2 f = *(const float2*)(fb + j * CC + lane * 2);
        float o0 = f.x - ctr.x, o1 = f.y - ctr.y;
        mx0 = fmaxf(mx0, o0); mn0 = fminf(mn0, o0);
        mx1 = fmaxf(mx1, o1); mn1 = fminf(mn1, o1);
        ss = fmaf(o0, o0, ss);
        ss = fmaf(o1, o1, ss);
    }

    const int ob = gw * CC + lane * 2;
    *(float2*)(g_mx + ob) = make_float2(mx0, mx1);
    *(float2*)(g_mn + ob) = make_float2(mn0, mn1);

#pragma unroll
    for (int off = 16; off; off >>= 1)
        ss += __shfl_xor_sync(FULL, ss, off);

    __shared__ float bs[8];
    if (lane == 0) bs[threadIdx.x >> 5] = ss;
    __syncthreads();
    if (threadIdx.x == 0) {
        g_part[blockIdx.x] = bs[0] + bs[1] + bs[2] + bs[3] +
                             bs[4] + bs[5] + bs[6] + bs[7];
    }
}

// ---------------------------------------------------------------------------
// Kernel 3: reduce partials -> g_inv = 1/(sigma + eps)
// ---------------------------------------------------------------------------
__global__ void reduce_kernel() {
    __shared__ float sm[256];
    float sacc = 0.f;
    for (int t = threadIdx.x; t < BB * NN / 8; t += 256) sacc += g_part[t];
    sm[threadIdx.x] = sacc;
    __syncthreads();
#pragma unroll
    for (int o = 128; o; o >>= 1) {
        if (threadIdx.x < o) sm[threadIdx.x] += sm[threadIdx.x + o];
        __syncthreads();
    }
    if (threadIdx.x == 0) {
        float sigma = sm[0] / (float)((long long)BB * NN * KNNK * CC);
        g_inv = 1.f / (sigma + 1e-5f);
    }
}

// ---------------------------------------------------------------------------
// Kernel 4: pooled = select(alpha>=0, max, min) * inv * alpha + beta
// (max over k commutes with the positive/negative scale)
// ---------------------------------------------------------------------------
__global__ void __launch_bounds__(256) final_kernel(const float* __restrict__ alpha,
                                                    const float* __restrict__ beta,
                                                    float* __restrict__ out) {
    const int idx = blockIdx.x * 256 + threadIdx.x;   // float2 index, 2M total
    const float inv = g_inv;
    const int c2 = idx & (CC / 2 - 1);
    const float a0 = alpha[c2 * 2], a1 = alpha[c2 * 2 + 1];
    const float b0 = beta[c2 * 2],  b1 = beta[c2 * 2 + 1];
    const float2 mx = ((const float2*)g_mx)[idx];
    const float2 mn = ((const float2*)g_mn)[idx];
    float v0 = (a0 >= 0.f) ? mx.x : mn.x;
    float v1 = (a1 >= 0.f) ? mx.y : mn.y;
    float2 r;
    r.x = fmaf(v0 * inv, a0, b0);
    r.y = fmaf(v1 * inv, a1, b1);
    ((float2*)out)[idx] = r;
}

extern "C" void kernel_launch(void* const* d_in, const int* in_sizes, int n_in,
                              void* d_out, int out_size) {
    const float* xyz   = (const float*)d_in[0];
    const float* feats = (const float*)d_in[1];
    const float* alpha = (const float*)d_in[2];
    const float* beta  = (const float*)d_in[3];
    float* out = (float*)d_out;
    (void)in_sizes; (void)n_in; (void)out_size;

    // Rotate ncu's skip-5 capture window onto knn_kernel (~3us overhead).
    nop_kernel<<<1, 1>>>();
    nop_kernel<<<1, 1>>>();
    nop_kernel<<<1, 1>>>();

    knn_kernel<<<BB * NN / 128, QB>>>(xyz);          // 512 blocks x 8 warps
    gather_kernel<<<BB * NN / 8, 256>>>(feats);
    reduce_kernel<<<1, 256>>>();
    final_kernel<<<BB * NN * CC / 512, 256>>>(alpha, beta, out);
}

// round 16
// speedup vs baseline: 1.5310x; 1.5310x over previous
#include <cuda_runtime.h>

#define BB    16
#define NN    4096
#define CC    64
#define KNNK  32
#define QB    128
#define NPAIRS 2048                      // all 4096 candidates resident
#define CAP   384

#define F_INF  __int_as_float(0x7f800000)
#define F_NINF __int_as_float(0xff800000)
#define FULL   0xFFFFFFFFu

typedef unsigned long long ull;

// Scratch (static device globals — allowed; no runtime allocation).
__device__ int   g_idx[BB * NN * KNNK];      // 8 MB
__device__ float g_mx[BB * NN * CC];         // 16 MB
__device__ float g_mn[BB * NN * CC];         // 16 MB
__device__ float g_part[BB * NN / 8];        // 8192 block partials
__device__ float g_inv;

// ---- Blackwell packed f32x2 ops (PTX-only; min/max.f32x2 do NOT exist) ----
__device__ __forceinline__ ull fma2(ull a, ull b, ull c) {
    ull d; asm("fma.rn.f32x2 %0, %1, %2, %3;" : "=l"(d) : "l"(a), "l"(b), "l"(c));
    return d;
}
__device__ __forceinline__ ull mul2(ull a, ull b) {
    ull d; asm("mul.rn.f32x2 %0, %1, %2;" : "=l"(d) : "l"(a), "l"(b));
    return d;
}
__device__ __forceinline__ ull pk2(float lo, float hi) {
    ull r; asm("mov.b64 %0, {%1, %2};" : "=l"(r) : "f"(lo), "f"(hi));
    return r;
}
__device__ __forceinline__ void up2(ull v, float& lo, float& hi) {
    asm("mov.b64 {%0, %1}, %2;" : "=f"(lo), "=f"(hi) : "l"(v));
}

// Branchless insert of c into ascending sorted 32-reg array (fallback only).
__device__ __forceinline__ void insert32(float (&sv)[KNNK], float c) {
#pragma unroll
    for (int u = 0; u < KNNK; u++) {
        float lo = fminf(sv[u], c);
        c = fmaxf(sv[u], c);
        sv[u] = lo;
    }
}

// Dummy no-op kernels: rotate ncu's "-s 5 -c 1" capture slot onto knn_kernel.
__global__ void nop_kernel() {}

// ---------------------------------------------------------------------------
// Kernel 1: exact 32-NN, one thread per query (occupancy hard-capped at
// 13.8 warps/SM — R10/R15 both proved splitting queries across more threads
// loses; the lever left is the per-iteration dependency chain).
// Sweep restructured into GROUPS OF 8 PAIRS: a branch-free LDS/FFMA2 block
// computes 16 distances with ILP 8, then 16 predicated accept-checks append
// to the record, with ONE flush vote per group (256 votes vs 2048 — R14's
// per-pair vote+branch fenced the scheduler; issue was 46%).
// Flush = bitonic sort of <=32-batch + bitonic merge-keep-min-32 (R14).
// Replay record for emission; per-thread full-recompute fallback on overflow.
// ---------------------------------------------------------------------------
__global__ void __launch_bounds__(QB) knn_kernel(const float* __restrict__ xyz) {
    __shared__ ulonglong2 s_xy[NPAIRS];              // {x01, y01}  32 KB
    __shared__ ull        s_z [NPAIRS];              //  z01        16 KB

    const int b = blockIdx.x >> 5;                   // 32 blocks per batch
    const int i = ((blockIdx.x & 31) << 7) + threadIdx.x;
    const float* xb = xyz + (size_t)b * (3 * NN);

    // Load + pack all candidates.
    for (int p = threadIdx.x; p < NPAIRS; p += QB) {
        float2 X = *(const float2*)(xb + 2 * p);
        float2 Y = *(const float2*)(xb + NN + 2 * p);
        float2 Z = *(const float2*)(xb + 2 * NN + 2 * p);
        s_xy[p] = make_ulonglong2(pk2(X.x, X.y), pk2(Y.x, Y.y));
        s_z[p]  = pk2(Z.x, Z.y);
    }

    const float xi = xb[i], yi = xb[NN + i], zi = xb[2 * NN + i];
    const ull AX = pk2(-2.f * xi, -2.f * xi);
    const ull AY = pk2(-2.f * yi, -2.f * yi);
    const ull AZ = pk2(-2.f * zi, -2.f * zi);
    __syncthreads();

    // d_rel = ||xj||^2 - 2 xi.xj, rounding identical to the R6/R8 champion.
    auto dist2 = [&](int p) -> ull {
        ulonglong2 XY = s_xy[p];
        ull Z  = s_z[p];
        ull nn = fma2(XY.x, XY.x, fma2(XY.y, XY.y, mul2(Z, Z)));
        return fma2(AX, XY.x, fma2(AY, XY.y, fma2(AZ, Z, nn)));
    };

    float2 rec[CAP];                                 // local mem (d, idx-bits)
    int rc = 0;                                      // total recorded
    int cnt = 0;                                     // recorded since flush
    bool ofl = false;

    float sv[KNNK];
#pragma unroll
    for (int u = 0; u < KNNK; u++) sv[u] = F_INF;
    float worst = F_INF;

    // Flush: exact top-32 update from the last `cnt` recorded distances.
    auto flush = [&]() {
        float t32[KNNK];
#pragma unroll
        for (int u = 0; u < KNNK; u++) {
            float v = F_INF;
            if (u < cnt) v = rec[rc - cnt + u].x;    // predicated LDL
            t32[u] = v;
        }
        // bitonic sort t32 ascending (ILP-16 network)
#pragma unroll
        for (int k = 2; k <= KNNK; k <<= 1) {
#pragma unroll
            for (int j = k >> 1; j > 0; j >>= 1) {
#pragma unroll
                for (int u = 0; u < KNNK; u++) {
                    int l = u ^ j;
                    if (l > u) {
                        bool up = ((u & k) == 0);
                        float lo = fminf(t32[u], t32[l]);
                        float hi = fmaxf(t32[u], t32[l]);
                        t32[u] = up ? lo : hi;
                        t32[l] = up ? hi : lo;
                    }
                }
            }
        }
        // keep-min-32 of sv ∪ t32: pairwise mins form a bitonic sequence
#pragma unroll
        for (int u = 0; u < KNNK; u++)
            sv[u] = fminf(sv[u], t32[KNNK - 1 - u]);
        // bitonic merge sv ascending (5 stages)
#pragma unroll
        for (int j = KNNK / 2; j > 0; j >>= 1) {
#pragma unroll
            for (int u = 0; u < KNNK; u++) {
                int l = u ^ j;
                if (l > u) {
                    float lo = fminf(sv[u], sv[l]);
                    float hi = fmaxf(sv[u], sv[l]);
                    sv[u] = lo; sv[l] = hi;
                }
            }
        }
        cnt = 0;
        worst = sv[KNNK - 1];
    };

    // ---- sweep: groups of 8 pairs, branch-free distance block, 1 vote ----
    for (int g = 0; g < NPAIRS; g += 8) {
        if (__any_sync(FULL, cnt >= 17)) flush();    // pass => cnt<=16, +16<=32
        float d[16];
#pragma unroll
        for (int u = 0; u < 8; u++)
            up2(dist2(g + u), d[2 * u], d[2 * u + 1]);
#pragma unroll
        for (int v = 0; v < 16; v++) {
            if (d[v] < worst) {
                if (rc < CAP) {
                    rec[rc++] = make_float2(d[v], __int_as_float(2 * g + v));
                    cnt++;
                } else ofl = true;
            }
        }
    }
    flush();                                         // leftovers

    float w = sv[KNNK - 1];                          // exact 32nd smallest
    int ties = 1;                                    // emissions allowed at ==w
#pragma unroll
    for (int u = 0; u < KNNK - 1; u++) ties += (sv[u] == w);

    const int base = (b * NN + i) * KNNK;
    if (!ofl) {
        // ---- fast path: replay recorded list -----------------------------
        int cnt2 = 0;
        for (int t = 0; t < rc; t++) {
            float2 r = rec[t];
            bool lt = r.x < w;
            bool eq = (r.x == w);
            if (lt | (eq & (ties > 0))) {
                g_idx[base + cnt2] = __float_as_int(r.y);
                cnt2++;
                ties -= eq ? 1 : 0;
            }
        }
    } else {
        // ---- fallback (never expected): full recompute + rescan ----------
#pragma unroll
        for (int u = 0; u < KNNK; u++) sv[u] = F_INF;
        for (int p = 0; p < NPAIRS; p++) {
            float d0, d1; up2(dist2(p), d0, d1);
            if (d0 < sv[KNNK - 1]) insert32(sv, d0);
            if (d1 < sv[KNNK - 1]) insert32(sv, d1);
        }
        w = sv[KNNK - 1];
        ties = 1;
#pragma unroll
        for (int u = 0; u < KNNK - 1; u++) ties += (sv[u] == w);
        int cnt2 = 0;
        for (int p = 0; p < NPAIRS; p++) {
            float d0, d1; up2(dist2(p), d0, d1);
            bool lt0 = d0 < w, eq0 = (d0 == w);
            bool lt1 = d1 < w, eq1 = (d1 == w);
            if (lt0 | (eq0 & (ties > 0))) {
                g_idx[base + cnt2] = 2 * p;
                cnt2++;
                ties -= eq0 ? 1 : 0;
            }
            if (lt1 | (eq1 & (ties > 0))) {
                g_idx[base + cnt2] = 2 * p + 1;
                cnt2++;
                ties -= eq1 ? 1 : 0;
            }
        }
    }
}

// ---------------------------------------------------------------------------
// Kernel 2: warp per (b,i). Lane = channel pair. Coalesced 256B row gathers.
// Produces per-channel max/min of offsets + block partial of sum(offset^2).
// ---------------------------------------------------------------------------
__global__ void __launch_bounds__(256) gather_kernel(const float* __restrict__ feats) {
    const int gw   = (blockIdx.x << 3) + (threadIdx.x >> 5);   // b*NN + i
    const int lane = threadIdx.x & 31;
    const int b = gw >> 12;
    const int i = gw & (NN - 1);
    const float* fb = feats + ((size_t)b << 18);               // b*NN*CC

    const float2 ctr = *(const float2*)(fb + i * CC + lane * 2);
    const int myid = g_idx[gw * KNNK + lane];

    float mx0 = F_NINF, mx1 = F_NINF;
    float mn0 = F_INF,  mn1 = F_INF;
    float ss = 0.f;

#pragma unroll
    for (int k = 0; k < KNNK; k++) {
        int j = __shfl_sync(FULL, myid, k);
        float2 f = *(const float2*)(fb + j * CC + lane * 2);
        float o0 = f.x - ctr.x, o1 = f.y - ctr.y;
        mx0 = fmaxf(mx0, o0); mn0 = fminf(mn0, o0);
        mx1 = fmaxf(mx1, o1); mn1 = fminf(mn1, o1);
        ss = fmaf(o0, o0, ss);
        ss = fmaf(o1, o1, ss);
    }

    const int ob = gw * CC + lane * 2;
    *(float2*)(g_mx + ob) = make_float2(mx0, mx1);
    *(float2*)(g_mn + ob) = make_float2(mn0, mn1);

#pragma unroll
    for (int off = 16; off; off >>= 1)
        ss += __shfl_xor_sync(FULL, ss, off);

    __shared__ float bs[8];
    if (lane == 0) bs[threadIdx.x >> 5] = ss;
    __syncthreads();
    if (threadIdx.x == 0) {
        g_part[blockIdx.x] = bs[0] + bs[1] + bs[2] + bs[3] +
                             bs[4] + bs[5] + bs[6] + bs[7];
    }
}

// ---------------------------------------------------------------------------
// Kernel 3: reduce partials -> g_inv = 1/(sigma + eps)
// ---------------------------------------------------------------------------
__global__ void reduce_kernel() {
    __shared__ float sm[256];
    float sacc = 0.f;
    for (int t = threadIdx.x; t < BB * NN / 8; t += 256) sacc += g_part[t];
    sm[threadIdx.x] = sacc;
    __syncthreads();
#pragma unroll
    for (int o = 128; o; o >>= 1) {
        if (threadIdx.x < o) sm[threadIdx.x] += sm[threadIdx.x + o];
        __syncthreads();
    }
    if (threadIdx.x == 0) {
        float sigma = sm[0] / (float)((long long)BB * NN * KNNK * CC);
        g_inv = 1.f / (sigma + 1e-5f);
    }
}

// ---------------------------------------------------------------------------
// Kernel 4: pooled = select(alpha>=0, max, min) * inv * alpha + beta
// (max over k commutes with the positive/negative scale)
// ---------------------------------------------------------------------------
__global__ void __launch_bounds__(256) final_kernel(const float* __restrict__ alpha,
                                                    const float* __restrict__ beta,
                                                    float* __restrict__ out) {
    const int idx = blockIdx.x * 256 + threadIdx.x;   // float2 index, 2M total
    const float inv = g_inv;
    const int c2 = idx & (CC / 2 - 1);
    const float a0 = alpha[c2 * 2], a1 = alpha[c2 * 2 + 1];
    const float b0 = beta[c2 * 2],  b1 = beta[c2 * 2 + 1];
    const float2 mx = ((const float2*)g_mx)[idx];
    const float2 mn = ((const float2*)g_mn)[idx];
    float v0 = (a0 >= 0.f) ? mx.x : mn.x;
    float v1 = (a1 >= 0.f) ? mx.y : mn.y;
    float2 r;
    r.x = fmaf(v0 * inv, a0, b0);
    r.y = fmaf(v1 * inv, a1, b1);
    ((float2*)out)[idx] = r;
}

extern "C" void kernel_launch(void* const* d_in, const int* in_sizes, int n_in,
                              void* d_out, int out_size) {
    const float* xyz   = (const float*)d_in[0];
    const float* feats = (const float*)d_in[1];
    const float* alpha = (const float*)d_in[2];
    const float* beta  = (const float*)d_in[3];
    float* out = (float*)d_out;
    (void)in_sizes; (void)n_in; (void)out_size;

    // Rotate ncu's skip-5 capture window onto knn_kernel (~3us overhead).
    nop_kernel<<<1, 1>>>();
    nop_kernel<<<1, 1>>>();
    nop_kernel<<<1, 1>>>();

    knn_kernel<<<BB * NN / QB, QB>>>(xyz);
    gather_kernel<<<BB * NN / 8, 256>>>(feats);
    reduce_kernel<<<1, 256>>>();
    final_kernel<<<BB * NN * CC / 512, 256>>>(alpha, beta, out);
}

// round 17
// speedup vs baseline: 1.7120x; 1.1182x over previous
#include <cuda_runtime.h>

#define BB    16
#define NN    4096
#define CC    64
#define KNNK  32
#define QB    128
#define NPAIRS 2048                      // all 4096 candidates resident
#define CAP   384

#define F_INF  __int_as_float(0x7f800000)
#define F_NINF __int_as_float(0xff800000)
#define FULL   0xFFFFFFFFu

typedef unsigned long long ull;

// Scratch (static device globals — allowed; no runtime allocation).
__device__ int   g_idx[BB * NN * KNNK];      // 8 MB
__device__ float g_mx[BB * NN * CC];         // 16 MB
__device__ float g_mn[BB * NN * CC];         // 16 MB
__device__ float g_part[BB * NN / 8];        // 8192 block partials
__device__ float g_inv;

// ---- Blackwell packed f32x2 ops (PTX-only; min/max.f32x2 do NOT exist) ----
__device__ __forceinline__ ull fma2(ull a, ull b, ull c) {
    ull d; asm("fma.rn.f32x2 %0, %1, %2, %3;" : "=l"(d) : "l"(a), "l"(b), "l"(c));
    return d;
}
__device__ __forceinline__ ull mul2(ull a, ull b) {
    ull d; asm("mul.rn.f32x2 %0, %1, %2;" : "=l"(d) : "l"(a), "l"(b));
    return d;
}
__device__ __forceinline__ ull pk2(float lo, float hi) {
    ull r; asm("mov.b64 %0, {%1, %2};" : "=l"(r) : "f"(lo), "f"(hi));
    return r;
}
__device__ __forceinline__ void up2(ull v, float& lo, float& hi) {
    asm("mov.b64 {%0, %1}, %2;" : "=f"(lo), "=f"(hi) : "l"(v));
}

// Branchless insert of c into ascending sorted 32-reg array (fallback only).
__device__ __forceinline__ void insert32(float (&sv)[KNNK], float c) {
#pragma unroll
    for (int u = 0; u < KNNK; u++) {
        float lo = fminf(sv[u], c);
        c = fmaxf(sv[u], c);
        sv[u] = lo;
    }
}

// Dummy no-op kernels: rotate ncu's "-s 5 -c 1" capture slot onto knn_kernel.
__global__ void nop_kernel() {}

// ---------------------------------------------------------------------------
// Kernel 1: exact 32-NN, one thread per query. Sweep in groups of 8 pairs:
// branch-free LDS/FFMA2 block computes 16 distances (ILP 8), then a 16-bit
// ACCEPT MASK is built with independent FSETP/SEL ops (R16's predicated
// appends serialized 16 STL+IADD on the rc carry — about half the sweep
// cost for ~0.1 real accepts/group). A rare ffs-driven store block appends
// accepts to the record (distance recomputed from smem for the dynamic bit,
// bit-identical). Record order/content identical to R16 => same flush
// (bitonic sort + merge-keep-min-32), same replay, same fallback.
// ---------------------------------------------------------------------------
__global__ void __launch_bounds__(QB) knn_kernel(const float* __restrict__ xyz) {
    __shared__ ulonglong2 s_xy[NPAIRS];              // {x01, y01}  32 KB
    __shared__ ull        s_z [NPAIRS];              //  z01        16 KB

    const int b = blockIdx.x >> 5;                   // 32 blocks per batch
    const int i = ((blockIdx.x & 31) << 7) + threadIdx.x;
    const float* xb = xyz + (size_t)b * (3 * NN);

    // Load + pack all candidates.
    for (int p = threadIdx.x; p < NPAIRS; p += QB) {
        float2 X = *(const float2*)(xb + 2 * p);
        float2 Y = *(const float2*)(xb + NN + 2 * p);
        float2 Z = *(const float2*)(xb + 2 * NN + 2 * p);
        s_xy[p] = make_ulonglong2(pk2(X.x, X.y), pk2(Y.x, Y.y));
        s_z[p]  = pk2(Z.x, Z.y);
    }

    const float xi = xb[i], yi = xb[NN + i], zi = xb[2 * NN + i];
    const ull AX = pk2(-2.f * xi, -2.f * xi);
    const ull AY = pk2(-2.f * yi, -2.f * yi);
    const ull AZ = pk2(-2.f * zi, -2.f * zi);
    __syncthreads();

    // d_rel = ||xj||^2 - 2 xi.xj, rounding identical to the R6/R8 champion.
    auto dist2 = [&](int p) -> ull {
        ulonglong2 XY = s_xy[p];
        ull Z  = s_z[p];
        ull nn = fma2(XY.x, XY.x, fma2(XY.y, XY.y, mul2(Z, Z)));
        return fma2(AX, XY.x, fma2(AY, XY.y, fma2(AZ, Z, nn)));
    };

    float2 rec[CAP];                                 // local mem (d, idx-bits)
    int rc = 0;                                      // total recorded
    int cnt = 0;                                     // recorded since flush
    bool ofl = false;

    float sv[KNNK];
#pragma unroll
    for (int u = 0; u < KNNK; u++) sv[u] = F_INF;
    float worst = F_INF;

    // Flush: exact top-32 update from the last `cnt` recorded distances.
    auto flush = [&]() {
        float t32[KNNK];
#pragma unroll
        for (int u = 0; u < KNNK; u++) {
            float v = F_INF;
            if (u < cnt) v = rec[rc - cnt + u].x;    // predicated LDL
            t32[u] = v;
        }
        // bitonic sort t32 ascending (ILP-16 network)
#pragma unroll
        for (int k = 2; k <= KNNK; k <<= 1) {
#pragma unroll
            for (int j = k >> 1; j > 0; j >>= 1) {
#pragma unroll
                for (int u = 0; u < KNNK; u++) {
                    int l = u ^ j;
                    if (l > u) {
                        bool up = ((u & k) == 0);
                        float lo = fminf(t32[u], t32[l]);
                        float hi = fmaxf(t32[u], t32[l]);
                        t32[u] = up ? lo : hi;
                        t32[l] = up ? hi : lo;
                    }
                }
            }
        }
        // keep-min-32 of sv ∪ t32: pairwise mins form a bitonic sequence
#pragma unroll
        for (int u = 0; u < KNNK; u++)
            sv[u] = fminf(sv[u], t32[KNNK - 1 - u]);
        // bitonic merge sv ascending (5 stages)
#pragma unroll
        for (int j = KNNK / 2; j > 0; j >>= 1) {
#pragma unroll
            for (int u = 0; u < KNNK; u++) {
                int l = u ^ j;
                if (l > u) {
                    float lo = fminf(sv[u], sv[l]);
                    float hi = fmaxf(sv[u], sv[l]);
                    sv[u] = lo; sv[l] = hi;
                }
            }
        }
        cnt = 0;
        worst = sv[KNNK - 1];
    };

    // ---- sweep: groups of 8 pairs, mask accepts, rare store block ---------
    for (int g = 0; g < NPAIRS; g += 8) {
        if (__any_sync(FULL, cnt >= 17)) flush();    // pass => cnt<=16, +16<=32
        float d[16];
#pragma unroll
        for (int u = 0; u < 8; u++)
            up2(dist2(g + u), d[2 * u], d[2 * u + 1]);

        int m = 0;
#pragma unroll
        for (int v = 0; v < 16; v++)
            m |= (d[v] < worst) ? (1 << v) : 0;      // independent FSETP/SEL

        if (__any_sync(FULL, m != 0)) {
            cnt += __popc(m);
            while (m) {                              // ~0.1 iters steady state
                int v = __ffs(m) - 1;
                m &= m - 1;
                // recompute from smem for dynamic v (bit-identical to d[v])
                float e0, e1; up2(dist2(g + (v >> 1)), e0, e1);
                float dv = (v & 1) ? e1 : e0;
                if (rc < CAP) rec[rc++] = make_float2(dv, __int_as_float(2 * g + v));
                else ofl = true;
            }
        }
    }
    flush();                                         // leftovers

    float w = sv[KNNK - 1];                          // exact 32nd smallest
    int ties = 1;                                    // emissions allowed at ==w
#pragma unroll
    for (int u = 0; u < KNNK - 1; u++) ties += (sv[u] == w);

    const int base = (b * NN + i) * KNNK;
    if (!ofl) {
        // ---- fast path: replay recorded list -----------------------------
        int cnt2 = 0;
        for (int t = 0; t < rc; t++) {
            float2 r = rec[t];
            bool lt = r.x < w;
            bool eq = (r.x == w);
            if (lt | (eq & (ties > 0))) {
                g_idx[base + cnt2] = __float_as_int(r.y);
                cnt2++;
                ties -= eq ? 1 : 0;
            }
        }
    } else {
        // ---- fallback (never expected): full recompute + rescan ----------
#pragma unroll
        for (int u = 0; u < KNNK; u++) sv[u] = F_INF;
        for (int p = 0; p < NPAIRS; p++) {
            float d0, d1; up2(dist2(p), d0, d1);
            if (d0 < sv[KNNK - 1]) insert32(sv, d0);
            if (d1 < sv[KNNK - 1]) insert32(sv, d1);
        }
        w = sv[KNNK - 1];
        ties = 1;
#pragma unroll
        for (int u = 0; u < KNNK - 1; u++) ties += (sv[u] == w);
        int cnt2 = 0;
        for (int p = 0; p < NPAIRS; p++) {
            float d0, d1; up2(dist2(p), d0, d1);
            bool lt0 = d0 < w, eq0 = (d0 == w);
            bool lt1 = d1 < w, eq1 = (d1 == w);
            if (lt0 | (eq0 & (ties > 0))) {
                g_idx[base + cnt2] = 2 * p;
                cnt2++;
                ties -= eq0 ? 1 : 0;
            }
            if (lt1 | (eq1 & (ties > 0))) {
                g_idx[base + cnt2] = 2 * p + 1;
                cnt2++;
                ties -= eq1 ? 1 : 0;
            }
        }
    }
}

// ---------------------------------------------------------------------------
// Kernel 2: warp per (b,i). Lane = channel pair. Coalesced 256B row gathers.
// Produces per-channel max/min of offsets + block partial of sum(offset^2).
// ---------------------------------------------------------------------------
__global__ void __launch_bounds__(256) gather_kernel(const float* __restrict__ feats) {
    const int gw   = (blockIdx.x << 3) + (threadIdx.x >> 5);   // b*NN + i
    const int lane = threadIdx.x & 31;
    const int b = gw >> 12;
    const int i = gw & (NN - 1);
    const float* fb = feats + ((size_t)b << 18);               // b*NN*CC

    const float2 ctr = *(const float2*)(fb + i * CC + lane * 2);
    const int myid = g_idx[gw * KNNK + lane];

    float mx0 = F_NINF, mx1 = F_NINF;
    float mn0 = F_INF,  mn1 = F_INF;
    float ss = 0.f;

#pragma unroll
    for (int k = 0; k < KNNK; k++) {
        int j = __shfl_sync(FULL, myid, k);
        float2 f = *(const float2*)(fb + j * CC + lane * 2);
        float o0 = f.x - ctr.x, o1 = f.y - ctr.y;
        mx0 = fmaxf(mx0, o0); mn0 = fminf(mn0, o0);
        mx1 = fmaxf(mx1, o1); mn1 = fminf(mn1, o1);
        ss = fmaf(o0, o0, ss);
        ss = fmaf(o1, o1, ss);
    }

    const int ob = gw * CC + lane * 2;
    *(float2*)(g_mx + ob) = make_float2(mx0, mx1);
    *(float2*)(g_mn + ob) = make_float2(mn0, mn1);

#pragma unroll
    for (int off = 16; off; off >>= 1)
        ss += __shfl_xor_sync(FULL, ss, off);

    __shared__ float bs[8];
    if (lane == 0) bs[threadIdx.x >> 5] = ss;
    __syncthreads();
    if (threadIdx.x == 0) {
        g_part[blockIdx.x] = bs[0] + bs[1] + bs[2] + bs[3] +
                             bs[4] + bs[5] + bs[6] + bs[7];
    }
}

// ---------------------------------------------------------------------------
// Kernel 3: reduce partials -> g_inv = 1/(sigma + eps)
// ---------------------------------------------------------------------------
__global__ void reduce_kernel() {
    __shared__ float sm[256];
    float sacc = 0.f;
    for (int t = threadIdx.x; t < BB * NN / 8; t += 256) sacc += g_part[t];
    sm[threadIdx.x] = sacc;
    __syncthreads();
#pragma unroll
    for (int o = 128; o; o >>= 1) {
        if (threadIdx.x < o) sm[threadIdx.x] += sm[threadIdx.x + o];
        __syncthreads();
    }
    if (threadIdx.x == 0) {
        float sigma = sm[0] / (float)((long long)BB * NN * KNNK * CC);
        g_inv = 1.f / (sigma + 1e-5f);
    }
}

// ---------------------------------------------------------------------------
// Kernel 4: pooled = select(alpha>=0, max, min) * inv * alpha + beta
// (max over k commutes with the positive/negative scale)
// ---------------------------------------------------------------------------
__global__ void __launch_bounds__(256) final_kernel(const float* __restrict__ alpha,
                                                    const float* __restrict__ beta,
                                                    float* __restrict__ out) {
    const int idx = blockIdx.x * 256 + threadIdx.x;   // float2 index, 2M total
    const float inv = g_inv;
    const int c2 = idx & (CC / 2 - 1);
    const float a0 = alpha[c2 * 2], a1 = alpha[c2 * 2 + 1];
    const float b0 = beta[c2 * 2],  b1 = beta[c2 * 2 + 1];
    const float2 mx = ((const float2*)g_mx)[idx];
    const float2 mn = ((const float2*)g_mn)[idx];
    float v0 = (a0 >= 0.f) ? mx.x : mn.x;
    float v1 = (a1 >= 0.f) ? mx.y : mn.y;
    float2 r;
    r.x = fmaf(v0 * inv, a0, b0);
    r.y = fmaf(v1 * inv, a1, b1);
    ((float2*)out)[idx] = r;
}

extern "C" void kernel_launch(void* const* d_in, const int* in_sizes, int n_in,
                              void* d_out, int out_size) {
    const float* xyz   = (const float*)d_in[0];
    const float* feats = (const float*)d_in[1];
    const float* alpha = (const float*)d_in[2];
    const float* beta  = (const float*)d_in[3];
    float* out = (float*)d_out;
    (void)in_sizes; (void)n_in; (void)out_size;

    // Rotate ncu's skip-5 capture window onto knn_kernel (~3us overhead).
    nop_kernel<<<1, 1>>>();
    nop_kernel<<<1, 1>>>();
    nop_kernel<<<1, 1>>>();

    knn_kernel<<<BB * NN / QB, QB>>>(xyz);
    gather_kernel<<<BB * NN / 8, 256>>>(feats);
    reduce_kernel<<<1, 256>>>();
    final_kernel<<<BB * NN * CC / 512, 256>>>(alpha, beta, out);
}